// round 5
// baseline (speedup 1.0000x reference)
#include <cuda_runtime.h>

// ---------------------------------------------------------------------------
// VQ-VAE forward: encoder (conv+BN+ReLU x3, 1x1 conv) -> VQ -> decoder
// (1x1 convT, convT+BN+ReLU x2, 3x3 conv). All fp32, NCHW.
// ---------------------------------------------------------------------------

#define FULLMASK 0xffffffffu
static const int NB = 32;  // partial blocks per channel for BN stats

// ---------------- scratch (static device memory; no allocations) -----------
__device__ float g_b1[33554432];   // 128*64*64*64   (h1, reused for g3)
__device__ float g_b2[16777216];   // 128*128*32*32  (h2, reused for g2)
__device__ float g_b3[6291456];    // 128*192*16*16  (h3, reused for g1)
__device__ float g_h4[8388608];    // 128*256*16*16  (Z)
__device__ float g_hq[8388608];    // quantized
__device__ float g_dot[8388608];   // Z . codebook_k
__device__ float g_part[256 * NB * 2];
__device__ float g_mean[256];
__device__ float g_istd[256];
__device__ float g_cc[256];
__device__ int   g_j[32768];
__device__ float g_lossp[4096];

// ---------------- BatchNorm (training-mode batch stats) --------------------
__global__ void bn_stats(const float* __restrict__ x, int C, int HW) {
    const int c = blockIdx.x, b = blockIdx.y, tid = threadIdx.x;
    const int nPer = 128 / NB;
    float s = 0.f, s2 = 0.f;
    for (int n = b * nPer; n < b * nPer + nPer; n++) {
        const float* p = x + (size_t)(n * C + c) * HW;
        for (int i = tid; i < HW; i += 256) { float v = p[i]; s += v; s2 = fmaf(v, v, s2); }
    }
    __shared__ float ss[256], ss2[256];
    ss[tid] = s; ss2[tid] = s2; __syncthreads();
    for (int o = 128; o; o >>= 1) {
        if (tid < o) { ss[tid] += ss[tid + o]; ss2[tid] += ss2[tid + o]; }
        __syncthreads();
    }
    if (tid == 0) {
        g_part[(c * NB + b) * 2]     = ss[0];
        g_part[(c * NB + b) * 2 + 1] = ss2[0];
    }
}

__global__ void bn_final(int C, float inv) {
    int c = threadIdx.x;
    if (c < C) {
        float s = 0.f, s2 = 0.f;
        for (int b = 0; b < NB; b++) { s += g_part[(c * NB + b) * 2]; s2 += g_part[(c * NB + b) * 2 + 1]; }
        float m = s * inv;
        float v = s2 * inv - m * m;
        g_mean[c] = m;
        g_istd[c] = 1.0f / sqrtf(v + 1e-5f);
    }
}

__global__ void bn_apply_relu(float* __restrict__ x, const float* __restrict__ gam,
                              const float* __restrict__ bet, int C, int HW) {
    int i = blockIdx.x * 256 + threadIdx.x;
    int c = (i / HW) % C;
    float v = (x[i] - g_mean[c]) * g_istd[c] * gam[c] + bet[c];
    x[i] = v > 0.f ? v : 0.f;
}

// ---------------- conv 3x3 s1 p1 (encoder first layer) ---------------------
template<int CIN, int H, int W, int PPT>
__global__ void conv3x3s1(const float* __restrict__ in, const float* __restrict__ w,
                          const float* __restrict__ bias, float* __restrict__ out, int COUT) {
    const int n = blockIdx.x, ocg = blockIdx.y, tile = blockIdx.z, tid = threadIdx.x;
    __shared__ float wsm[8][CIN][9];
    for (int i = tid; i < 8 * CIN * 9; i += 256) {
        int j = i / (CIN * 9), r = i % (CIN * 9);
        wsm[j][r / 9][r % 9] = w[(size_t)(ocg * 8 + j) * CIN * 9 + r];
    }
    __syncthreads();
    float acc[PPT][8] = {};
    int oy[PPT], ox[PPT];
#pragma unroll
    for (int p = 0; p < PPT; p++) {
        int pos = tile * (256 * PPT) + p * 256 + tid;
        oy[p] = pos / W; ox[p] = pos % W;
    }
    for (int ic = 0; ic < CIN; ic++) {
        const float* ip = in + (size_t)(n * CIN + ic) * H * W;
#pragma unroll
        for (int ky = 0; ky < 3; ky++) {
#pragma unroll
            for (int kx = 0; kx < 3; kx++) {
                float wr[8];
#pragma unroll
                for (int j = 0; j < 8; j++) wr[j] = wsm[j][ic][ky * 3 + kx];
#pragma unroll
                for (int p = 0; p < PPT; p++) {
                    int iy = oy[p] + ky - 1, ix = ox[p] + kx - 1;
                    float v = (iy >= 0 && iy < H && ix >= 0 && ix < W) ? ip[iy * W + ix] : 0.f;
#pragma unroll
                    for (int j = 0; j < 8; j++) acc[p][j] = fmaf(v, wr[j], acc[p][j]);
                }
            }
        }
    }
#pragma unroll
    for (int p = 0; p < PPT; p++)
#pragma unroll
        for (int j = 0; j < 8; j++)
            out[((size_t)(n * COUT + ocg * 8 + j) * H + oy[p]) * W + ox[p]] = acc[p][j] + bias[ocg * 8 + j];
}

// ---------------- conv 4x4 s2 p1 --------------------------------------------
template<int CIN, int IH, int IW, int COUT, int OH, int OW, int PPT>
__global__ void conv4x4s2(const float* __restrict__ in, const float* __restrict__ w,
                          const float* __restrict__ bias, float* __restrict__ out) {
    const int ICC = 64;
    const int n = blockIdx.x, ocg = blockIdx.y, tile = blockIdx.z, tid = threadIdx.x;
    __shared__ float wsm[8][ICC][16];
    float acc[PPT][8] = {};
    int oy[PPT], ox[PPT];
#pragma unroll
    for (int p = 0; p < PPT; p++) {
        int pos = tile * (256 * PPT) + p * 256 + tid;
        oy[p] = pos / OW; ox[p] = pos % OW;
    }
    for (int ic0 = 0; ic0 < CIN; ic0 += ICC) {
        __syncthreads();
        for (int i = tid; i < 8 * ICC * 16; i += 256) {
            int j = i / (ICC * 16), r = i % (ICC * 16);
            wsm[j][r / 16][r % 16] = w[(size_t)(ocg * 8 + j) * CIN * 16 + (size_t)ic0 * 16 + r];
        }
        __syncthreads();
        for (int ic = 0; ic < ICC; ic++) {
            const float* ip = in + (size_t)(n * CIN + ic0 + ic) * IH * IW;
#pragma unroll
            for (int ky = 0; ky < 4; ky++) {
#pragma unroll
                for (int kx = 0; kx < 4; kx++) {
                    float wr[8];
#pragma unroll
                    for (int j = 0; j < 8; j++) wr[j] = wsm[j][ic][ky * 4 + kx];
#pragma unroll
                    for (int p = 0; p < PPT; p++) {
                        int iy = oy[p] * 2 - 1 + ky, ix = ox[p] * 2 - 1 + kx;
                        float v = (iy >= 0 && iy < IH && ix >= 0 && ix < IW) ? ip[iy * IW + ix] : 0.f;
#pragma unroll
                        for (int j = 0; j < 8; j++) acc[p][j] = fmaf(v, wr[j], acc[p][j]);
                    }
                }
            }
        }
    }
#pragma unroll
    for (int p = 0; p < PPT; p++)
#pragma unroll
        for (int j = 0; j < 8; j++)
            out[((size_t)(n * COUT + ocg * 8 + j) * OH + oy[p]) * OW + ox[p]] = acc[p][j] + bias[ocg * 8 + j];
}

// ---------------- convTranspose 4x4 s2 p1 ----------------------------------
// out[oy] gets input iy with ky = oy + 1 - 2*iy, ky in {p, p+2}, p = (oy+1)&1.
template<int CIN, int IH, int IW, int COUT, int OH, int OW, int PPT>
__global__ void convT4x4s2(const float* __restrict__ in, const float* __restrict__ w,
                           const float* __restrict__ bias, float* __restrict__ out) {
    const int ICC = 64;
    const int n = blockIdx.x, ocg = blockIdx.y, tile = blockIdx.z, tid = threadIdx.x;
    __shared__ float wsm[ICC][8][16];
    float acc[PPT][8] = {};
    int oy[PPT], ox[PPT];
#pragma unroll
    for (int p = 0; p < PPT; p++) {
        int pos = tile * (256 * PPT) + p * 256 + tid;
        oy[p] = pos / OW; ox[p] = pos % OW;
    }
    const int ky0 = (oy[0] + 1) & 1;
    const int kx0 = (ox[0] + 1) & 1;
    int iyA[PPT], iyB[PPT], ixA[PPT], ixB[PPT];
#pragma unroll
    for (int p = 0; p < PPT; p++) {
        int a = (oy[p] + 1 - ky0) >> 1; iyA[p] = (a < IH) ? a : -1; iyB[p] = (a - 1 >= 0) ? a - 1 : -1;
        int c = (ox[p] + 1 - kx0) >> 1; ixA[p] = (c < IW) ? c : -1; ixB[p] = (c - 1 >= 0) ? c - 1 : -1;
    }
    for (int ic0 = 0; ic0 < CIN; ic0 += ICC) {
        __syncthreads();
        for (int i = tid; i < ICC * 8 * 16; i += 256) {
            int ic = i / (8 * 16), r = i % (8 * 16);
            int j = r / 16, t = r % 16;
            wsm[ic][j][t] = w[(size_t)(ic0 + ic) * COUT * 16 + (size_t)(ocg * 8 + j) * 16 + t];
        }
        __syncthreads();
        for (int ic = 0; ic < ICC; ic++) {
            const float* ip = in + (size_t)(n * CIN + ic0 + ic) * IH * IW;
#pragma unroll
            for (int a = 0; a < 2; a++) {
#pragma unroll
                for (int b = 0; b < 2; b++) {
                    int tap = (ky0 + a * 2) * 4 + (kx0 + b * 2);
                    float wr[8];
#pragma unroll
                    for (int j = 0; j < 8; j++) wr[j] = wsm[ic][j][tap];
#pragma unroll
                    for (int p = 0; p < PPT; p++) {
                        int iy = a ? iyB[p] : iyA[p];
                        int ix = b ? ixB[p] : ixA[p];
                        float v = (iy >= 0 && ix >= 0) ? ip[iy * IW + ix] : 0.f;
#pragma unroll
                        for (int j = 0; j < 8; j++) acc[p][j] = fmaf(v, wr[j], acc[p][j]);
                    }
                }
            }
        }
    }
#pragma unroll
    for (int p = 0; p < PPT; p++)
#pragma unroll
        for (int j = 0; j < 8; j++)
            out[((size_t)(n * COUT + ocg * 8 + j) * OH + oy[p]) * OW + ox[p]] = acc[p][j] + bias[ocg * 8 + j];
}

// ---------------- 1x1 conv / matmul (also used for VQ dot) ------------------
template<int CIN, int COUT, int HW, bool WT, bool HASB>
__global__ void conv1x1(const float* __restrict__ in, const float* __restrict__ w,
                        const float* __restrict__ bias, float* __restrict__ out) {
    const int n = blockIdx.x, ocg = blockIdx.y, tid = threadIdx.x;
    __shared__ float wsm[8][CIN];
    for (int i = tid; i < 8 * CIN; i += 256) {
        int j = i / CIN, ic = i % CIN;
        wsm[j][ic] = WT ? w[(size_t)ic * COUT + ocg * 8 + j] : w[(size_t)(ocg * 8 + j) * CIN + ic];
    }
    __syncthreads();
    float acc[8] = {};
    const float* ip = in + (size_t)n * CIN * HW + tid;
#pragma unroll 4
    for (int ic = 0; ic < CIN; ic++) {
        float v = ip[(size_t)ic * HW];
#pragma unroll
        for (int j = 0; j < 8; j++) acc[j] = fmaf(v, wsm[j][ic], acc[j]);
    }
#pragma unroll
    for (int j = 0; j < 8; j++) {
        float b = HASB ? bias[ocg * 8 + j] : 0.f;
        out[(size_t)(n * COUT + ocg * 8 + j) * HW + tid] = acc[j] + b;
    }
}

// ---------------- VQ --------------------------------------------------------
// cc[k] = ||codebook_k||^2, correctly rounded (fp64 accumulate -> fp32)
__global__ void cc_kernel(const float* __restrict__ cb) {
    int k = threadIdx.x;  // 256 threads, 1 block
    double s = 0.0;
    for (int d = 0; d < 256; d++) { double v = (double)cb[k * 256 + d]; s = fma(v, v, s); }
    g_cc[k] = (float)s;
}

__device__ __forceinline__ unsigned fenc(float f) {
    unsigned u = __float_as_uint(f);
    return (u & 0x80000000u) ? ~u : (u | 0x80000000u);
}

// One warp per pixel. Emulates the reference fp32 arithmetic:
//   d2_k = fl32( fl32(zz + cc_k) - 2*dot_k )
// with zz correctly rounded (fp64->fp32). The big zz offset (~||Z||^2)
// quantizes distances to the fp32 ulp grid, merging near-ties into exact
// ties that the reference argmin resolves by FIRST INDEX — so we must too.
__global__ void vq_argmin(const float* __restrict__ dot, const float* __restrict__ z,
                          const float* __restrict__ cb) {
    const int warp = threadIdx.x >> 5, lane = threadIdx.x & 31;
    const int pix = blockIdx.x * 8 + warp;
    const int n = pix >> 8, p = pix & 255;
    const float* dp = dot + (size_t)n * 65536 + p;

    // zz = ||Z_pix||^2, fp64 accumulate then round to fp32
    double zzd = 0.0;
    for (int d = lane; d < 256; d += 32) {
        double v = (double)z[(size_t)(n * 256 + d) * 256 + p];
        zzd = fma(v, v, zzd);
    }
#pragma unroll
    for (int o = 16; o; o >>= 1) zzd += __shfl_xor_sync(FULLMASK, zzd, o);
    const float zz = (float)zzd;

    // argmin over 256 codes on the emulated fp32 d2, first-index tie-break
    unsigned long long bestK = ~0ull;
#pragma unroll
    for (int q = 0; q < 8; q++) {
        int k = lane + q * 32;
        float t1 = __fadd_rn(zz, g_cc[k]);
        float d2 = __fsub_rn(t1, 2.0f * dp[(size_t)k * 256]);
        unsigned long long key = ((unsigned long long)fenc(d2) << 32) | (unsigned)k;
        if (key < bestK) bestK = key;
    }
#pragma unroll
    for (int o = 16; o; o >>= 1) {
        unsigned long long v = __shfl_xor_sync(FULLMASK, bestK, o);
        if (v < bestK) bestK = v;
    }
    const int j = (int)(bestK & 0xffffffffu);

    // exact commit loss for this pixel (fp32)
    float ls = 0.f;
    for (int d = lane; d < 256; d += 32) {
        float zd = z[(size_t)(n * 256 + d) * 256 + p];
        float df = zd - cb[j * 256 + d];
        ls = fmaf(df, df, ls);
    }
#pragma unroll
    for (int o = 16; o; o >>= 1) ls += __shfl_xor_sync(FULLMASK, ls, o);

    __shared__ float wls[8];
    if (lane == 0) { wls[warp] = ls; g_j[pix] = j; }
    __syncthreads();
    if (threadIdx.x == 0) {
        float t = 0.f;
        for (int i = 0; i < 8; i++) t += wls[i];
        g_lossp[blockIdx.x] = t;
    }
}

__global__ void loss_final(float* __restrict__ out) {
    __shared__ float sm[256];
    int t = threadIdx.x;
    float s = 0.f;
    for (int i = t; i < 4096; i += 256) s += g_lossp[i];
    sm[t] = s; __syncthreads();
    for (int o = 128; o; o >>= 1) { if (t < o) sm[t] += sm[t + o]; __syncthreads(); }
    if (t == 0) {
        float L = sm[0] / 32768.f;
        out[0] = L;  // loss_commit
        out[1] = L;  // loss_code (identical in forward)
    }
}

__global__ void vq_gather(const float* __restrict__ cb, float* __restrict__ hq) {
    int i = blockIdx.x * 256 + threadIdx.x;   // 8388608 total
    int p = i & 255, d = (i >> 8) & 255, n = i >> 16;
    hq[i] = cb[g_j[n * 256 + p] * 256 + d];
}

// ---------------- final 3x3 conv (64 -> 3) ----------------------------------
__global__ void conv3x3_out(const float* __restrict__ in, const float* __restrict__ w,
                            const float* __restrict__ bias, float* __restrict__ out) {
    const int n = blockIdx.x, tile = blockIdx.y, tid = threadIdx.x;
    __shared__ float wsm[3][64][9];
    for (int i = tid; i < 3 * 64 * 9; i += 256)
        wsm[i / 576][(i / 9) % 64][i % 9] = w[i];
    __syncthreads();
    float acc[4][3] = {};
    int oy[4], ox[4];
#pragma unroll
    for (int p = 0; p < 4; p++) {
        int pos = tile * 1024 + p * 256 + tid;
        oy[p] = pos >> 6; ox[p] = pos & 63;
    }
    for (int ic = 0; ic < 64; ic++) {
        const float* ip = in + (size_t)(n * 64 + ic) * 4096;
#pragma unroll
        for (int ky = 0; ky < 3; ky++) {
#pragma unroll
            for (int kx = 0; kx < 3; kx++) {
                float w0 = wsm[0][ic][ky * 3 + kx];
                float w1 = wsm[1][ic][ky * 3 + kx];
                float w2 = wsm[2][ic][ky * 3 + kx];
#pragma unroll
                for (int p = 0; p < 4; p++) {
                    int iy = oy[p] + ky - 1, ix = ox[p] + kx - 1;
                    float v = (iy >= 0 && iy < 64 && ix >= 0 && ix < 64) ? ip[iy * 64 + ix] : 0.f;
                    acc[p][0] = fmaf(v, w0, acc[p][0]);
                    acc[p][1] = fmaf(v, w1, acc[p][1]);
                    acc[p][2] = fmaf(v, w2, acc[p][2]);
                }
            }
        }
    }
#pragma unroll
    for (int p = 0; p < 4; p++)
#pragma unroll
        for (int oc = 0; oc < 3; oc++)
            out[(size_t)(n * 3 + oc) * 4096 + oy[p] * 64 + ox[p]] = acc[p][oc] + bias[oc];
}

// ---------------------------------------------------------------------------
static void run_bn(float* buf, int C, int HW, const float* g, const float* b) {
    bn_stats<<<dim3(C, NB), 256>>>(buf, C, HW);
    bn_final<<<1, 256>>>(C, 1.0f / (128.0f * (float)HW));
    int total = 128 * C * HW;
    bn_apply_relu<<<total / 256, 256>>>(buf, g, b, C, HW);
}

extern "C" void kernel_launch(void* const* d_in, const int* in_sizes, int n_in,
                              void* d_out, int out_size) {
    const float* x    = (const float*)d_in[0];
    const float* cb   = (const float*)d_in[1];
    const float* e_w1 = (const float*)d_in[2];
    const float* e_b1 = (const float*)d_in[3];
    const float* e_g1 = (const float*)d_in[4];
    const float* e_be1= (const float*)d_in[5];
    const float* e_w2 = (const float*)d_in[6];
    const float* e_b2 = (const float*)d_in[7];
    const float* e_g2 = (const float*)d_in[8];
    const float* e_be2= (const float*)d_in[9];
    const float* e_w3 = (const float*)d_in[10];
    const float* e_b3 = (const float*)d_in[11];
    const float* e_g3 = (const float*)d_in[12];
    const float* e_be3= (const float*)d_in[13];
    const float* e_w4 = (const float*)d_in[14];
    const float* e_b4 = (const float*)d_in[15];
    const float* d_w1 = (const float*)d_in[16];
    const float* d_b1 = (const float*)d_in[17];
    const float* d_g1 = (const float*)d_in[18];
    const float* d_be1= (const float*)d_in[19];
    const float* d_w2 = (const float*)d_in[20];
    const float* d_b2 = (const float*)d_in[21];
    const float* d_g2 = (const float*)d_in[22];
    const float* d_be2= (const float*)d_in[23];
    const float* d_w3 = (const float*)d_in[24];
    const float* d_b3 = (const float*)d_in[25];
    const float* d_g3 = (const float*)d_in[26];
    const float* d_be3= (const float*)d_in[27];
    const float* d_w4 = (const float*)d_in[28];
    const float* d_b4 = (const float*)d_in[29];
    float* out = (float*)d_out;

    float *b1, *b2, *b3, *h4, *hq, *dotb;
    cudaGetSymbolAddress((void**)&b1,   g_b1);
    cudaGetSymbolAddress((void**)&b2,   g_b2);
    cudaGetSymbolAddress((void**)&b3,   g_b3);
    cudaGetSymbolAddress((void**)&h4,   g_h4);
    cudaGetSymbolAddress((void**)&hq,   g_hq);
    cudaGetSymbolAddress((void**)&dotb, g_dot);

    // ---------------- encoder ----------------
    conv3x3s1<3, 64, 64, 4><<<dim3(128, 8, 4), 256>>>(x, e_w1, e_b1, b1, 64);
    run_bn(b1, 64, 4096, e_g1, e_be1);

    conv4x4s2<64, 64, 64, 128, 32, 32, 4><<<dim3(128, 16, 1), 256>>>(b1, e_w2, e_b2, b2);
    run_bn(b2, 128, 1024, e_g2, e_be2);

    conv4x4s2<128, 32, 32, 192, 16, 16, 1><<<dim3(128, 24, 1), 256>>>(b2, e_w3, e_b3, b3);
    run_bn(b3, 192, 256, e_g3, e_be3);

    conv1x1<192, 256, 256, false, true><<<dim3(128, 32), 256>>>(b3, e_w4, e_b4, h4);

    // ---------------- vector quantization ----------------
    cc_kernel<<<1, 256>>>(cb);
    conv1x1<256, 256, 256, false, false><<<dim3(128, 32), 256>>>(h4, cb, nullptr, dotb);
    vq_argmin<<<4096, 256>>>(dotb, h4, cb);
    loss_final<<<1, 256>>>(out + (out_size - 2));
    vq_gather<<<32768, 256>>>(cb, hq);

    // ---------------- decoder ----------------
    conv1x1<256, 192, 256, true, true><<<dim3(128, 24), 256>>>(hq, d_w1, d_b1, b3);
    run_bn(b3, 192, 256, d_g1, d_be1);

    convT4x4s2<192, 16, 16, 128, 32, 32, 4><<<dim3(128, 16, 1), 256>>>(b3, d_w2, d_b2, b2);
    run_bn(b2, 128, 1024, d_g2, d_be2);

    convT4x4s2<128, 32, 32, 64, 64, 64, 4><<<dim3(128, 8, 4), 256>>>(b2, d_w3, d_b3, b1);
    run_bn(b1, 64, 4096, d_g3, d_be3);

    conv3x3_out<<<dim3(128, 4), 256>>>(b1, d_w4, d_b4, out);
}

// round 6
// speedup vs baseline: 1.1405x; 1.1405x over previous
#include <cuda_runtime.h>

// ---------------------------------------------------------------------------
// VQ-VAE forward: encoder (conv+BN+ReLU x3, 1x1 conv) -> VQ -> decoder
// (1x1 convT, convT+BN+ReLU x2, 3x3 conv). All fp32, NCHW.
// Convs use packed fma.rn.f32x2 (FFMA2): 2x fp32 FLOP/cycle, bit-identical.
// ---------------------------------------------------------------------------

#define FULLMASK 0xffffffffu
static const int NB = 32;  // partial blocks per channel for BN stats

// ---------------- scratch (static device memory; no allocations) -----------
__device__ float g_b1[33554432];   // 128*64*64*64   (h1, reused for g3)
__device__ float g_b2[16777216];   // 128*128*32*32  (h2, reused for g2)
__device__ float g_b3[6291456];    // 128*192*16*16  (h3, reused for g1)
__device__ float g_h4[8388608];    // 128*256*16*16  (Z)
__device__ float g_hq[8388608];    // quantized
__device__ float g_dot[8388608];   // Z . codebook_k
__device__ float g_part[256 * NB * 2];
__device__ float g_mean[256];
__device__ float g_istd[256];
__device__ float g_cc[256];
__device__ int   g_j[32768];
__device__ float g_lossp[4096];

// ---------------- packed f32x2 helpers --------------------------------------
typedef unsigned long long u64;

__device__ __forceinline__ u64 pack2(float lo, float hi) {
    u64 r;
    asm("mov.b64 %0, {%1, %2};" : "=l"(r) : "r"(__float_as_uint(lo)), "r"(__float_as_uint(hi)));
    return r;
}
__device__ __forceinline__ void unpack2(u64 v, float& lo, float& hi) {
    unsigned a, b;
    asm("mov.b64 {%0, %1}, %2;" : "=r"(a), "=r"(b) : "l"(v));
    lo = __uint_as_float(a); hi = __uint_as_float(b);
}
__device__ __forceinline__ void ffma2(u64& acc, u64 a, u64 b) {
    asm("fma.rn.f32x2 %0, %1, %2, %0;" : "+l"(acc) : "l"(a), "l"(b));
}

// ---------------- BatchNorm (training-mode batch stats) --------------------
__global__ void bn_stats(const float* __restrict__ x, int C, int HW) {
    const int c = blockIdx.x, b = blockIdx.y, tid = threadIdx.x;
    const int nPer = 128 / NB;
    float s = 0.f, s2 = 0.f;
    for (int n = b * nPer; n < b * nPer + nPer; n++) {
        const float* p = x + (size_t)(n * C + c) * HW;
        for (int i = tid; i < HW; i += 256) { float v = p[i]; s += v; s2 = fmaf(v, v, s2); }
    }
    __shared__ float ss[256], ss2[256];
    ss[tid] = s; ss2[tid] = s2; __syncthreads();
    for (int o = 128; o; o >>= 1) {
        if (tid < o) { ss[tid] += ss[tid + o]; ss2[tid] += ss2[tid + o]; }
        __syncthreads();
    }
    if (tid == 0) {
        g_part[(c * NB + b) * 2]     = ss[0];
        g_part[(c * NB + b) * 2 + 1] = ss2[0];
    }
}

__global__ void bn_final(int C, float inv) {
    int c = threadIdx.x;
    if (c < C) {
        float s = 0.f, s2 = 0.f;
        for (int b = 0; b < NB; b++) { s += g_part[(c * NB + b) * 2]; s2 += g_part[(c * NB + b) * 2 + 1]; }
        float m = s * inv;
        float v = s2 * inv - m * m;
        g_mean[c] = m;
        g_istd[c] = 1.0f / sqrtf(v + 1e-5f);
    }
}

// float4-vectorized apply; arithmetic per element identical to scalar version.
template<int C, int HW>
__global__ void bn_apply_relu4(float4* __restrict__ x, const float* __restrict__ gam,
                               const float* __restrict__ bet) {
    const int i4 = blockIdx.x * 256 + threadIdx.x;
    const int c = (i4 / (HW / 4)) % C;
    const float m = g_mean[c], is = g_istd[c], g = gam[c], be = bet[c];
    float4 v = x[i4];
    v.x = (v.x - m) * is * g + be; v.x = v.x > 0.f ? v.x : 0.f;
    v.y = (v.y - m) * is * g + be; v.y = v.y > 0.f ? v.y : 0.f;
    v.z = (v.z - m) * is * g + be; v.z = v.z > 0.f ? v.z : 0.f;
    v.w = (v.w - m) * is * g + be; v.w = v.w > 0.f ? v.w : 0.f;
    x[i4] = v;
}

// ---------------- conv 3x3 s1 p1 (encoder first layer) ---------------------
template<int CIN, int H, int W, int PPT>
__global__ void conv3x3s1(const float* __restrict__ in, const float* __restrict__ w,
                          const float* __restrict__ bias, float* __restrict__ out, int COUT) {
    const int n = blockIdx.x, ocg = blockIdx.y, tile = blockIdx.z, tid = threadIdx.x;
    __shared__ float wsm[CIN][9][8];
    for (int i = tid; i < 8 * CIN * 9; i += 256) {
        int j = i / (CIN * 9), r = i % (CIN * 9);
        wsm[r / 9][r % 9][j] = w[(size_t)(ocg * 8 + j) * CIN * 9 + r];
    }
    __syncthreads();
    u64 acc[PPT][4] = {};
    int oy[PPT], ox[PPT];
#pragma unroll
    for (int p = 0; p < PPT; p++) {
        int pos = tile * (256 * PPT) + p * 256 + tid;
        oy[p] = pos / W; ox[p] = pos % W;
    }
    for (int ic = 0; ic < CIN; ic++) {
        const float* ip = in + (size_t)(n * CIN + ic) * H * W;
#pragma unroll
        for (int tap = 0; tap < 9; tap++) {
            const int ky = tap / 3, kx = tap % 3;
            const u64* wp = reinterpret_cast<const u64*>(&wsm[ic][tap][0]);
            u64 w0 = wp[0], w1 = wp[1], w2 = wp[2], w3 = wp[3];
#pragma unroll
            for (int p = 0; p < PPT; p++) {
                int iy = oy[p] + ky - 1, ix = ox[p] + kx - 1;
                float v = (iy >= 0 && iy < H && ix >= 0 && ix < W) ? ip[iy * W + ix] : 0.f;
                u64 vv = pack2(v, v);
                ffma2(acc[p][0], vv, w0); ffma2(acc[p][1], vv, w1);
                ffma2(acc[p][2], vv, w2); ffma2(acc[p][3], vv, w3);
            }
        }
    }
#pragma unroll
    for (int p = 0; p < PPT; p++)
#pragma unroll
        for (int q = 0; q < 4; q++) {
            float a, b; unpack2(acc[p][q], a, b);
            out[((size_t)(n * COUT + ocg * 8 + 2 * q) * H + oy[p]) * W + ox[p]]     = a + bias[ocg * 8 + 2 * q];
            out[((size_t)(n * COUT + ocg * 8 + 2 * q + 1) * H + oy[p]) * W + ox[p]] = b + bias[ocg * 8 + 2 * q + 1];
        }
}

// ---------------- conv 4x4 s2 p1 --------------------------------------------
template<int CIN, int IH, int IW, int COUT, int OH, int OW, int PPT>
__global__ void conv4x4s2(const float* __restrict__ in, const float* __restrict__ w,
                          const float* __restrict__ bias, float* __restrict__ out) {
    const int ICC = 64;
    const int n = blockIdx.x, ocg = blockIdx.y, tile = blockIdx.z, tid = threadIdx.x;
    __shared__ float wsm[ICC][16][8];
    u64 acc[PPT][4] = {};
    int oy[PPT], ox[PPT];
#pragma unroll
    for (int p = 0; p < PPT; p++) {
        int pos = tile * (256 * PPT) + p * 256 + tid;
        oy[p] = pos / OW; ox[p] = pos % OW;
    }
    for (int ic0 = 0; ic0 < CIN; ic0 += ICC) {
        __syncthreads();
        for (int i = tid; i < 8 * ICC * 16; i += 256) {
            int j = i / (ICC * 16), r = i % (ICC * 16);
            wsm[r / 16][r % 16][j] = w[(size_t)(ocg * 8 + j) * CIN * 16 + (size_t)ic0 * 16 + r];
        }
        __syncthreads();
        for (int ic = 0; ic < ICC; ic++) {
            const float* ip = in + (size_t)(n * CIN + ic0 + ic) * IH * IW;
#pragma unroll
            for (int tap = 0; tap < 16; tap++) {
                const int ky = tap >> 2, kx = tap & 3;
                const u64* wp = reinterpret_cast<const u64*>(&wsm[ic][tap][0]);
                u64 w0 = wp[0], w1 = wp[1], w2 = wp[2], w3 = wp[3];
#pragma unroll
                for (int p = 0; p < PPT; p++) {
                    int iy = oy[p] * 2 - 1 + ky, ix = ox[p] * 2 - 1 + kx;
                    float v = (iy >= 0 && iy < IH && ix >= 0 && ix < IW) ? ip[iy * IW + ix] : 0.f;
                    u64 vv = pack2(v, v);
                    ffma2(acc[p][0], vv, w0); ffma2(acc[p][1], vv, w1);
                    ffma2(acc[p][2], vv, w2); ffma2(acc[p][3], vv, w3);
                }
            }
        }
    }
#pragma unroll
    for (int p = 0; p < PPT; p++)
#pragma unroll
        for (int q = 0; q < 4; q++) {
            float a, b; unpack2(acc[p][q], a, b);
            out[((size_t)(n * COUT + ocg * 8 + 2 * q) * OH + oy[p]) * OW + ox[p]]     = a + bias[ocg * 8 + 2 * q];
            out[((size_t)(n * COUT + ocg * 8 + 2 * q + 1) * OH + oy[p]) * OW + ox[p]] = b + bias[ocg * 8 + 2 * q + 1];
        }
}

// ---------------- convTranspose 4x4 s2 p1 ----------------------------------
// out[oy] gets input iy with ky = oy + 1 - 2*iy, ky in {p, p+2}, p = (oy+1)&1.
template<int CIN, int IH, int IW, int COUT, int OH, int OW, int PPT>
__global__ void convT4x4s2(const float* __restrict__ in, const float* __restrict__ w,
                           const float* __restrict__ bias, float* __restrict__ out) {
    const int ICC = 64;
    const int n = blockIdx.x, ocg = blockIdx.y, tile = blockIdx.z, tid = threadIdx.x;
    __shared__ float wsm[ICC][16][8];
    u64 acc[PPT][4] = {};
    int oy[PPT], ox[PPT];
#pragma unroll
    for (int p = 0; p < PPT; p++) {
        int pos = tile * (256 * PPT) + p * 256 + tid;
        oy[p] = pos / OW; ox[p] = pos % OW;
    }
    const int ky0 = (oy[0] + 1) & 1;
    const int kx0 = (ox[0] + 1) & 1;
    int iyA[PPT], iyB[PPT], ixA[PPT], ixB[PPT];
#pragma unroll
    for (int p = 0; p < PPT; p++) {
        int a = (oy[p] + 1 - ky0) >> 1; iyA[p] = (a < IH) ? a : -1; iyB[p] = (a - 1 >= 0) ? a - 1 : -1;
        int c = (ox[p] + 1 - kx0) >> 1; ixA[p] = (c < IW) ? c : -1; ixB[p] = (c - 1 >= 0) ? c - 1 : -1;
    }
    for (int ic0 = 0; ic0 < CIN; ic0 += ICC) {
        __syncthreads();
        for (int i = tid; i < ICC * 8 * 16; i += 256) {
            int ic = i / 128, r = i % 128;
            int j = r / 16, t = r % 16;
            wsm[ic][t][j] = w[(size_t)(ic0 + ic) * COUT * 16 + (size_t)(ocg * 8 + j) * 16 + t];
        }
        __syncthreads();
        for (int ic = 0; ic < ICC; ic++) {
            const float* ip = in + (size_t)(n * CIN + ic0 + ic) * IH * IW;
#pragma unroll
            for (int a = 0; a < 2; a++) {
#pragma unroll
                for (int b = 0; b < 2; b++) {
                    const int tap = (ky0 + a * 2) * 4 + (kx0 + b * 2);
                    const u64* wp = reinterpret_cast<const u64*>(&wsm[ic][tap][0]);
                    u64 w0 = wp[0], w1 = wp[1], w2 = wp[2], w3 = wp[3];
#pragma unroll
                    for (int p = 0; p < PPT; p++) {
                        int iy = a ? iyB[p] : iyA[p];
                        int ix = b ? ixB[p] : ixA[p];
                        float v = (iy >= 0 && ix >= 0) ? ip[iy * IW + ix] : 0.f;
                        u64 vv = pack2(v, v);
                        ffma2(acc[p][0], vv, w0); ffma2(acc[p][1], vv, w1);
                        ffma2(acc[p][2], vv, w2); ffma2(acc[p][3], vv, w3);
                    }
                }
            }
        }
    }
#pragma unroll
    for (int p = 0; p < PPT; p++)
#pragma unroll
        for (int q = 0; q < 4; q++) {
            float a, b; unpack2(acc[p][q], a, b);
            out[((size_t)(n * COUT + ocg * 8 + 2 * q) * OH + oy[p]) * OW + ox[p]]     = a + bias[ocg * 8 + 2 * q];
            out[((size_t)(n * COUT + ocg * 8 + 2 * q + 1) * OH + oy[p]) * OW + ox[p]] = b + bias[ocg * 8 + 2 * q + 1];
        }
}

// ---------------- 1x1 conv / matmul (also used for VQ dot) ------------------
template<int CIN, int COUT, int HW, bool WT, bool HASB>
__global__ void conv1x1(const float* __restrict__ in, const float* __restrict__ w,
                        const float* __restrict__ bias, float* __restrict__ out) {
    const int n = blockIdx.x, ocg = blockIdx.y, tid = threadIdx.x;
    __shared__ float wsm[CIN][8];
    if (WT) {
        for (int i = tid; i < 8 * CIN; i += 256) {
            int ic = i / 8, j = i % 8;
            wsm[ic][j] = w[(size_t)ic * COUT + ocg * 8 + j];
        }
    } else {
        for (int i = tid; i < 8 * CIN; i += 256) {
            int j = i / CIN, ic = i % CIN;
            wsm[ic][j] = w[(size_t)(ocg * 8 + j) * CIN + ic];
        }
    }
    __syncthreads();
    u64 acc[4] = {};
    const float* ip = in + (size_t)n * CIN * HW + tid;
#pragma unroll 4
    for (int ic = 0; ic < CIN; ic++) {
        float v = ip[(size_t)ic * HW];
        u64 vv = pack2(v, v);
        const u64* wp = reinterpret_cast<const u64*>(&wsm[ic][0]);
        ffma2(acc[0], vv, wp[0]); ffma2(acc[1], vv, wp[1]);
        ffma2(acc[2], vv, wp[2]); ffma2(acc[3], vv, wp[3]);
    }
#pragma unroll
    for (int q = 0; q < 4; q++) {
        float a, b; unpack2(acc[q], a, b);
        float b0 = HASB ? bias[ocg * 8 + 2 * q] : 0.f;
        float b1 = HASB ? bias[ocg * 8 + 2 * q + 1] : 0.f;
        out[(size_t)(n * COUT + ocg * 8 + 2 * q) * HW + tid]     = a + b0;
        out[(size_t)(n * COUT + ocg * 8 + 2 * q + 1) * HW + tid] = b + b1;
    }
}

// ---------------- VQ --------------------------------------------------------
// cc[k] = ||codebook_k||^2, correctly rounded (fp64 accumulate -> fp32)
__global__ void cc_kernel(const float* __restrict__ cb) {
    int k = threadIdx.x;  // 256 threads, 1 block
    double s = 0.0;
    for (int d = 0; d < 256; d++) { double v = (double)cb[k * 256 + d]; s = fma(v, v, s); }
    g_cc[k] = (float)s;
}

__device__ __forceinline__ unsigned fenc(float f) {
    unsigned u = __float_as_uint(f);
    return (u & 0x80000000u) ? ~u : (u | 0x80000000u);
}

// One warp per pixel. Emulates the reference fp32 arithmetic:
//   d2_k = fl32( fl32(zz + cc_k) - 2*dot_k )
// with zz correctly rounded (fp64->fp32). First-index tie-break.
__global__ void vq_argmin(const float* __restrict__ dot, const float* __restrict__ z,
                          const float* __restrict__ cb) {
    const int warp = threadIdx.x >> 5, lane = threadIdx.x & 31;
    const int pix = blockIdx.x * 8 + warp;
    const int n = pix >> 8, p = pix & 255;
    const float* dp = dot + (size_t)n * 65536 + p;

    double zzd = 0.0;
    for (int d = lane; d < 256; d += 32) {
        double v = (double)z[(size_t)(n * 256 + d) * 256 + p];
        zzd = fma(v, v, zzd);
    }
#pragma unroll
    for (int o = 16; o; o >>= 1) zzd += __shfl_xor_sync(FULLMASK, zzd, o);
    const float zz = (float)zzd;

    unsigned long long bestK = ~0ull;
#pragma unroll
    for (int q = 0; q < 8; q++) {
        int k = lane + q * 32;
        float t1 = __fadd_rn(zz, g_cc[k]);
        float d2 = __fsub_rn(t1, 2.0f * dp[(size_t)k * 256]);
        unsigned long long key = ((unsigned long long)fenc(d2) << 32) | (unsigned)k;
        if (key < bestK) bestK = key;
    }
#pragma unroll
    for (int o = 16; o; o >>= 1) {
        unsigned long long v = __shfl_xor_sync(FULLMASK, bestK, o);
        if (v < bestK) bestK = v;
    }
    const int j = (int)(bestK & 0xffffffffu);

    float ls = 0.f;
    for (int d = lane; d < 256; d += 32) {
        float zd = z[(size_t)(n * 256 + d) * 256 + p];
        float df = zd - cb[j * 256 + d];
        ls = fmaf(df, df, ls);
    }
#pragma unroll
    for (int o = 16; o; o >>= 1) ls += __shfl_xor_sync(FULLMASK, ls, o);

    __shared__ float wls[8];
    if (lane == 0) { wls[warp] = ls; g_j[pix] = j; }
    __syncthreads();
    if (threadIdx.x == 0) {
        float t = 0.f;
        for (int i = 0; i < 8; i++) t += wls[i];
        g_lossp[blockIdx.x] = t;
    }
}

__global__ void loss_final(float* __restrict__ out) {
    __shared__ float sm[256];
    int t = threadIdx.x;
    float s = 0.f;
    for (int i = t; i < 4096; i += 256) s += g_lossp[i];
    sm[t] = s; __syncthreads();
    for (int o = 128; o; o >>= 1) { if (t < o) sm[t] += sm[t + o]; __syncthreads(); }
    if (t == 0) {
        float L = sm[0] / 32768.f;
        out[0] = L;  // loss_commit
        out[1] = L;  // loss_code (identical in forward)
    }
}

__global__ void vq_gather(const float* __restrict__ cb, float* __restrict__ hq) {
    int i = blockIdx.x * 256 + threadIdx.x;   // 8388608 total
    int p = i & 255, d = (i >> 8) & 255, n = i >> 16;
    hq[i] = cb[g_j[n * 256 + p] * 256 + d];
}

// ---------------- final 3x3 conv (64 -> 3) ----------------------------------
__global__ void conv3x3_out(const float* __restrict__ in, const float* __restrict__ w,
                            const float* __restrict__ bias, float* __restrict__ out) {
    const int n = blockIdx.x, tile = blockIdx.y, tid = threadIdx.x;
    __shared__ float wsm[64][9][4];   // [ic][tap][oc], slot 3 unused (pair align)
    for (int i = tid; i < 3 * 64 * 9; i += 256) {
        int oc = i / 576, r = i % 576;
        wsm[r / 9][r % 9][oc] = w[i];
    }
    __syncthreads();
    u64 acc01[4] = {};
    float acc2[4] = {};
    int oy[4], ox[4];
#pragma unroll
    for (int p = 0; p < 4; p++) {
        int pos = tile * 1024 + p * 256 + tid;
        oy[p] = pos >> 6; ox[p] = pos & 63;
    }
    for (int ic = 0; ic < 64; ic++) {
        const float* ip = in + (size_t)(n * 64 + ic) * 4096;
#pragma unroll
        for (int tap = 0; tap < 9; tap++) {
            const int ky = tap / 3, kx = tap % 3;
            u64 w01 = *reinterpret_cast<const u64*>(&wsm[ic][tap][0]);
            float w2 = wsm[ic][tap][2];
#pragma unroll
            for (int p = 0; p < 4; p++) {
                int iy = oy[p] + ky - 1, ix = ox[p] + kx - 1;
                float v = (iy >= 0 && iy < 64 && ix >= 0 && ix < 64) ? ip[iy * 64 + ix] : 0.f;
                ffma2(acc01[p], pack2(v, v), w01);
                acc2[p] = fmaf(v, w2, acc2[p]);
            }
        }
    }
#pragma unroll
    for (int p = 0; p < 4; p++) {
        float a, b; unpack2(acc01[p], a, b);
        out[(size_t)(n * 3 + 0) * 4096 + oy[p] * 64 + ox[p]] = a + bias[0];
        out[(size_t)(n * 3 + 1) * 4096 + oy[p] * 64 + ox[p]] = b + bias[1];
        out[(size_t)(n * 3 + 2) * 4096 + oy[p] * 64 + ox[p]] = acc2[p] + bias[2];
    }
}

// ---------------------------------------------------------------------------
template<int C, int HW>
static void run_bn(float* buf, const float* g, const float* b) {
    bn_stats<<<dim3(C, NB), 256>>>(buf, C, HW);
    bn_final<<<1, 256>>>(C, 1.0f / (128.0f * (float)HW));
    int total4 = 128 * C * HW / 4;
    bn_apply_relu4<C, HW><<<total4 / 256, 256>>>((float4*)buf, g, b);
}

extern "C" void kernel_launch(void* const* d_in, const int* in_sizes, int n_in,
                              void* d_out, int out_size) {
    const float* x    = (const float*)d_in[0];
    const float* cb   = (const float*)d_in[1];
    const float* e_w1 = (const float*)d_in[2];
    const float* e_b1 = (const float*)d_in[3];
    const float* e_g1 = (const float*)d_in[4];
    const float* e_be1= (const float*)d_in[5];
    const float* e_w2 = (const float*)d_in[6];
    const float* e_b2 = (const float*)d_in[7];
    const float* e_g2 = (const float*)d_in[8];
    const float* e_be2= (const float*)d_in[9];
    const float* e_w3 = (const float*)d_in[10];
    const float* e_b3 = (const float*)d_in[11];
    const float* e_g3 = (const float*)d_in[12];
    const float* e_be3= (const float*)d_in[13];
    const float* e_w4 = (const float*)d_in[14];
    const float* e_b4 = (const float*)d_in[15];
    const float* d_w1 = (const float*)d_in[16];
    const float* d_b1 = (const float*)d_in[17];
    const float* d_g1 = (const float*)d_in[18];
    const float* d_be1= (const float*)d_in[19];
    const float* d_w2 = (const float*)d_in[20];
    const float* d_b2 = (const float*)d_in[21];
    const float* d_g2 = (const float*)d_in[22];
    const float* d_be2= (const float*)d_in[23];
    const float* d_w3 = (const float*)d_in[24];
    const float* d_b3 = (const float*)d_in[25];
    const float* d_g3 = (const float*)d_in[26];
    const float* d_be3= (const float*)d_in[27];
    const float* d_w4 = (const float*)d_in[28];
    const float* d_b4 = (const float*)d_in[29];
    float* out = (float*)d_out;

    float *b1, *b2, *b3, *h4, *hq, *dotb;
    cudaGetSymbolAddress((void**)&b1,   g_b1);
    cudaGetSymbolAddress((void**)&b2,   g_b2);
    cudaGetSymbolAddress((void**)&b3,   g_b3);
    cudaGetSymbolAddress((void**)&h4,   g_h4);
    cudaGetSymbolAddress((void**)&hq,   g_hq);
    cudaGetSymbolAddress((void**)&dotb, g_dot);

    // ---------------- encoder ----------------
    conv3x3s1<3, 64, 64, 4><<<dim3(128, 8, 4), 256>>>(x, e_w1, e_b1, b1, 64);
    run_bn<64, 4096>(b1, e_g1, e_be1);

    conv4x4s2<64, 64, 64, 128, 32, 32, 4><<<dim3(128, 16, 1), 256>>>(b1, e_w2, e_b2, b2);
    run_bn<128, 1024>(b2, e_g2, e_be2);

    conv4x4s2<128, 32, 32, 192, 16, 16, 1><<<dim3(128, 24, 1), 256>>>(b2, e_w3, e_b3, b3);
    run_bn<192, 256>(b3, e_g3, e_be3);

    conv1x1<192, 256, 256, false, true><<<dim3(128, 32), 256>>>(b3, e_w4, e_b4, h4);

    // ---------------- vector quantization ----------------
    cc_kernel<<<1, 256>>>(cb);
    conv1x1<256, 256, 256, false, false><<<dim3(128, 32), 256>>>(h4, cb, nullptr, dotb);
    vq_argmin<<<4096, 256>>>(dotb, h4, cb);
    loss_final<<<1, 256>>>(out + (out_size - 2));
    vq_gather<<<32768, 256>>>(cb, hq);

    // ---------------- decoder ----------------
    conv1x1<256, 192, 256, true, true><<<dim3(128, 24), 256>>>(hq, d_w1, d_b1, b3);
    run_bn<192, 256>(b3, d_g1, d_be1);

    convT4x4s2<192, 16, 16, 128, 32, 32, 4><<<dim3(128, 16, 1), 256>>>(b3, d_w2, d_b2, b2);
    run_bn<128, 1024>(b2, d_g2, d_be2);

    convT4x4s2<128, 32, 32, 64, 64, 64, 4><<<dim3(128, 8, 4), 256>>>(b2, d_w3, d_b3, b1);
    run_bn<64, 4096>(b1, d_g3, d_be3);

    conv3x3_out<<<dim3(128, 4), 256>>>(b1, d_w4, d_b4, out);
}

// round 10
// speedup vs baseline: 1.2185x; 1.0684x over previous
#include <cuda_runtime.h>

// ---------------------------------------------------------------------------
// VQ-VAE forward: encoder (conv+BN+ReLU x3, 1x1 conv) -> VQ -> decoder
// (1x1 convT, convT+BN+ReLU x2, 3x3 conv). All fp32, NCHW.
// Convs: packed fma.rn.f32x2 (FFMA2) + 16 output channels per thread
// (halves LDG issue vs 8). Accumulation order bit-identical across rounds.
// ---------------------------------------------------------------------------

#define FULLMASK 0xffffffffu
static const int NB = 32;  // partial blocks per channel for BN stats

// ---------------- scratch (static device memory; no allocations) -----------
__device__ float g_b1[33554432];   // 128*64*64*64   (h1, reused for g3)
__device__ float g_b2[16777216];   // 128*128*32*32  (h2, reused for g2)
__device__ float g_b3[6291456];    // 128*192*16*16  (h3, reused for g1)
__device__ float g_h4[8388608];    // 128*256*16*16  (Z)
__device__ float g_hq[8388608];    // quantized
__device__ float g_dot[8388608];   // Z . codebook_k
__device__ float g_part[256 * NB * 2];
__device__ float g_mean[256];
__device__ float g_istd[256];
__device__ float g_cc[256];
__device__ int   g_j[32768];
__device__ float g_lossp[4096];

// ---------------- packed f32x2 helpers --------------------------------------
typedef unsigned long long u64;

__device__ __forceinline__ u64 pack2(float lo, float hi) {
    u64 r;
    asm("mov.b64 %0, {%1, %2};" : "=l"(r) : "r"(__float_as_uint(lo)), "r"(__float_as_uint(hi)));
    return r;
}
__device__ __forceinline__ void unpack2(u64 v, float& lo, float& hi) {
    unsigned a, b;
    asm("mov.b64 {%0, %1}, %2;" : "=r"(a), "=r"(b) : "l"(v));
    lo = __uint_as_float(a); hi = __uint_as_float(b);
}
__device__ __forceinline__ void ffma2(u64& acc, u64 a, u64 b) {
    asm("fma.rn.f32x2 %0, %1, %2, %0;" : "+l"(acc) : "l"(a), "l"(b));
}

// ---------------- BatchNorm (training-mode batch stats) --------------------
__global__ void bn_stats(const float4* __restrict__ x, int C, int HW4) {
    const int c = blockIdx.x, b = blockIdx.y, tid = threadIdx.x;
    const int nPer = 128 / NB;
    float s = 0.f, s2 = 0.f;
    for (int n = b * nPer; n < b * nPer + nPer; n++) {
        const float4* p = x + (size_t)(n * C + c) * HW4;
        for (int i = tid; i < HW4; i += 256) {
            float4 v = p[i];
            s += v.x; s2 = fmaf(v.x, v.x, s2);
            s += v.y; s2 = fmaf(v.y, v.y, s2);
            s += v.z; s2 = fmaf(v.z, v.z, s2);
            s += v.w; s2 = fmaf(v.w, v.w, s2);
        }
    }
    __shared__ float ss[256], ss2[256];
    ss[tid] = s; ss2[tid] = s2; __syncthreads();
    for (int o = 128; o; o >>= 1) {
        if (tid < o) { ss[tid] += ss[tid + o]; ss2[tid] += ss2[tid + o]; }
        __syncthreads();
    }
    if (tid == 0) {
        g_part[(c * NB + b) * 2]     = ss[0];
        g_part[(c * NB + b) * 2 + 1] = ss2[0];
    }
}

__global__ void bn_final(int C, float inv) {
    int c = threadIdx.x;
    if (c < C) {
        float s = 0.f, s2 = 0.f;
        for (int b = 0; b < NB; b++) { s += g_part[(c * NB + b) * 2]; s2 += g_part[(c * NB + b) * 2 + 1]; }
        float m = s * inv;
        float v = s2 * inv - m * m;
        g_mean[c] = m;
        g_istd[c] = 1.0f / sqrtf(v + 1e-5f);
    }
}

template<int C, int HW>
__global__ void bn_apply_relu4(float4* __restrict__ x, const float* __restrict__ gam,
                               const float* __restrict__ bet) {
    const int i4 = blockIdx.x * 256 + threadIdx.x;
    const int c = (i4 / (HW / 4)) % C;
    const float m = g_mean[c], is = g_istd[c], g = gam[c], be = bet[c];
    float4 v = x[i4];
    v.x = (v.x - m) * is * g + be; v.x = v.x > 0.f ? v.x : 0.f;
    v.y = (v.y - m) * is * g + be; v.y = v.y > 0.f ? v.y : 0.f;
    v.z = (v.z - m) * is * g + be; v.z = v.z > 0.f ? v.z : 0.f;
    v.w = (v.w - m) * is * g + be; v.w = v.w > 0.f ? v.w : 0.f;
    x[i4] = v;
}

// ---------------- conv 3x3 s1 p1 (encoder first layer), 16 oc/thread -------
template<int CIN, int H, int W, int PPT>
__global__ void conv3x3s1(const float* __restrict__ in, const float* __restrict__ w,
                          const float* __restrict__ bias, float* __restrict__ out, int COUT) {
    const int n = blockIdx.x, ocg = blockIdx.y, tile = blockIdx.z, tid = threadIdx.x;
    __shared__ float wsm[CIN][9][16];
    for (int i = tid; i < CIN * 9 * 16; i += 256) {
        int ic = i / 144, r = i % 144, tap = r / 16, oc = r % 16;
        wsm[ic][tap][oc] = w[(size_t)(ocg * 16 + oc) * CIN * 9 + ic * 9 + tap];
    }
    __syncthreads();
    u64 acc[PPT][8] = {};
    int oy[PPT], ox[PPT];
#pragma unroll
    for (int p = 0; p < PPT; p++) {
        int pos = tile * (256 * PPT) + p * 256 + tid;
        oy[p] = pos / W; ox[p] = pos % W;
    }
    for (int ic = 0; ic < CIN; ic++) {
        const float* ip = in + (size_t)(n * CIN + ic) * H * W;
#pragma unroll
        for (int tap = 0; tap < 9; tap++) {
            const int ky = tap / 3, kx = tap % 3;
            const u64* wp = reinterpret_cast<const u64*>(&wsm[ic][tap][0]);
            u64 w8[8];
#pragma unroll
            for (int q = 0; q < 8; q++) w8[q] = wp[q];
#pragma unroll
            for (int p = 0; p < PPT; p++) {
                int iy = oy[p] + ky - 1, ix = ox[p] + kx - 1;
                float v = (iy >= 0 && iy < H && ix >= 0 && ix < W) ? ip[iy * W + ix] : 0.f;
                u64 vv = pack2(v, v);
#pragma unroll
                for (int q = 0; q < 8; q++) ffma2(acc[p][q], vv, w8[q]);
            }
        }
    }
#pragma unroll
    for (int p = 0; p < PPT; p++)
#pragma unroll
        for (int q = 0; q < 8; q++) {
            float a, b; unpack2(acc[p][q], a, b);
            out[((size_t)(n * COUT + ocg * 16 + 2 * q) * H + oy[p]) * W + ox[p]]     = a + bias[ocg * 16 + 2 * q];
            out[((size_t)(n * COUT + ocg * 16 + 2 * q + 1) * H + oy[p]) * W + ox[p]] = b + bias[ocg * 16 + 2 * q + 1];
        }
}

// ---------------- conv 4x4 s2 p1, 16 oc/thread ------------------------------
template<int CIN, int IH, int IW, int COUT, int OH, int OW, int PPT>
__global__ void conv4x4s2(const float* __restrict__ in, const float* __restrict__ w,
                          const float* __restrict__ bias, float* __restrict__ out) {
    const int ICC = 32;
    const int n = blockIdx.x, ocg = blockIdx.y, tile = blockIdx.z, tid = threadIdx.x;
    __shared__ float wsm[ICC][16][16];   // [ic][tap][oc]
    u64 acc[PPT][8] = {};
    int oy[PPT], ox[PPT];
#pragma unroll
    for (int p = 0; p < PPT; p++) {
        int pos = tile * (256 * PPT) + p * 256 + tid;
        oy[p] = pos / OW; ox[p] = pos % OW;
    }
    for (int ic0 = 0; ic0 < CIN; ic0 += ICC) {
        __syncthreads();
        for (int i = tid; i < ICC * 16 * 16; i += 256) {
            int ic = i / 256, r = i % 256, tap = r / 16, oc = r % 16;
            wsm[ic][tap][oc] = w[(size_t)(ocg * 16 + oc) * CIN * 16 + (size_t)(ic0 + ic) * 16 + tap];
        }
        __syncthreads();
        for (int ic = 0; ic < ICC; ic++) {
            const float* ip = in + (size_t)(n * CIN + ic0 + ic) * IH * IW;
#pragma unroll
            for (int tap = 0; tap < 16; tap++) {
                const int ky = tap >> 2, kx = tap & 3;
                const u64* wp = reinterpret_cast<const u64*>(&wsm[ic][tap][0]);
                u64 w8[8];
#pragma unroll
                for (int q = 0; q < 8; q++) w8[q] = wp[q];
#pragma unroll
                for (int p = 0; p < PPT; p++) {
                    int iy = oy[p] * 2 - 1 + ky, ix = ox[p] * 2 - 1 + kx;
                    float v = (iy >= 0 && iy < IH && ix >= 0 && ix < IW) ? ip[iy * IW + ix] : 0.f;
                    u64 vv = pack2(v, v);
#pragma unroll
                    for (int q = 0; q < 8; q++) ffma2(acc[p][q], vv, w8[q]);
                }
            }
        }
    }
#pragma unroll
    for (int p = 0; p < PPT; p++)
#pragma unroll
        for (int q = 0; q < 8; q++) {
            float a, b; unpack2(acc[p][q], a, b);
            out[((size_t)(n * COUT + ocg * 16 + 2 * q) * OH + oy[p]) * OW + ox[p]]     = a + bias[ocg * 16 + 2 * q];
            out[((size_t)(n * COUT + ocg * 16 + 2 * q + 1) * OH + oy[p]) * OW + ox[p]] = b + bias[ocg * 16 + 2 * q + 1];
        }
}

// ---------------- convTranspose 4x4 s2 p1, 16 oc/thread ---------------------
// out[oy] gets input iy with ky = oy + 1 - 2*iy, ky in {p, p+2}, p = (oy+1)&1.
template<int CIN, int IH, int IW, int COUT, int OH, int OW, int PPT>
__global__ void convT4x4s2(const float* __restrict__ in, const float* __restrict__ w,
                           const float* __restrict__ bias, float* __restrict__ out) {
    const int ICC = 32;
    const int n = blockIdx.x, ocg = blockIdx.y, tile = blockIdx.z, tid = threadIdx.x;
    __shared__ float wsm[ICC][16][16];   // [ic][tap][oc]
    u64 acc[PPT][8] = {};
    int oy[PPT], ox[PPT];
#pragma unroll
    for (int p = 0; p < PPT; p++) {
        int pos = tile * (256 * PPT) + p * 256 + tid;
        oy[p] = pos / OW; ox[p] = pos % OW;
    }
    const int ky0 = (oy[0] + 1) & 1;
    const int kx0 = (ox[0] + 1) & 1;
    int iyA[PPT], iyB[PPT], ixA[PPT], ixB[PPT];
#pragma unroll
    for (int p = 0; p < PPT; p++) {
        int a = (oy[p] + 1 - ky0) >> 1; iyA[p] = (a < IH) ? a : -1; iyB[p] = (a - 1 >= 0) ? a - 1 : -1;
        int c = (ox[p] + 1 - kx0) >> 1; ixA[p] = (c < IW) ? c : -1; ixB[p] = (c - 1 >= 0) ? c - 1 : -1;
    }
    for (int ic0 = 0; ic0 < CIN; ic0 += ICC) {
        __syncthreads();
        for (int i = tid; i < ICC * 16 * 16; i += 256) {
            int ic = i / 256, r = i % 256, tap = r / 16, oc = r % 16;
            wsm[ic][tap][oc] = w[(size_t)(ic0 + ic) * COUT * 16 + (size_t)(ocg * 16 + oc) * 16 + tap];
        }
        __syncthreads();
        for (int ic = 0; ic < ICC; ic++) {
            const float* ip = in + (size_t)(n * CIN + ic0 + ic) * IH * IW;
#pragma unroll
            for (int a = 0; a < 2; a++) {
#pragma unroll
                for (int b = 0; b < 2; b++) {
                    const int tap = (ky0 + a * 2) * 4 + (kx0 + b * 2);
                    const u64* wp = reinterpret_cast<const u64*>(&wsm[ic][tap][0]);
                    u64 w8[8];
#pragma unroll
                    for (int q = 0; q < 8; q++) w8[q] = wp[q];
#pragma unroll
                    for (int p = 0; p < PPT; p++) {
                        int iy = a ? iyB[p] : iyA[p];
                        int ix = b ? ixB[p] : ixA[p];
                        float v = (iy >= 0 && ix >= 0) ? ip[iy * IW + ix] : 0.f;
                        u64 vv = pack2(v, v);
#pragma unroll
                        for (int q = 0; q < 8; q++) ffma2(acc[p][q], vv, w8[q]);
                    }
                }
            }
        }
    }
#pragma unroll
    for (int p = 0; p < PPT; p++)
#pragma unroll
        for (int q = 0; q < 8; q++) {
            float a, b; unpack2(acc[p][q], a, b);
            out[((size_t)(n * COUT + ocg * 16 + 2 * q) * OH + oy[p]) * OW + ox[p]]     = a + bias[ocg * 16 + 2 * q];
            out[((size_t)(n * COUT + ocg * 16 + 2 * q + 1) * OH + oy[p]) * OW + ox[p]] = b + bias[ocg * 16 + 2 * q + 1];
        }
}

// ---------------- 1x1 conv / matmul, 16 oc/thread ---------------------------
template<int CIN, int COUT, int HW, bool WT, bool HASB>
__global__ void conv1x1(const float* __restrict__ in, const float* __restrict__ w,
                        const float* __restrict__ bias, float* __restrict__ out) {
    const int n = blockIdx.x, ocg = blockIdx.y, tid = threadIdx.x;
    __shared__ float wsm[CIN][16];
    if (WT) {
        for (int i = tid; i < 16 * CIN; i += 256) {
            int ic = i / 16, j = i % 16;
            wsm[ic][j] = w[(size_t)ic * COUT + ocg * 16 + j];
        }
    } else {
        for (int i = tid; i < 16 * CIN; i += 256) {
            int j = i / CIN, ic = i % CIN;
            wsm[ic][j] = w[(size_t)(ocg * 16 + j) * CIN + ic];
        }
    }
    __syncthreads();
    u64 acc[8] = {};
    const float* ip = in + (size_t)n * CIN * HW + tid;
#pragma unroll 4
    for (int ic = 0; ic < CIN; ic++) {
        float v = ip[(size_t)ic * HW];
        u64 vv = pack2(v, v);
        const u64* wp = reinterpret_cast<const u64*>(&wsm[ic][0]);
#pragma unroll
        for (int q = 0; q < 8; q++) ffma2(acc[q], vv, wp[q]);
    }
#pragma unroll
    for (int q = 0; q < 8; q++) {
        float a, b; unpack2(acc[q], a, b);
        float b0 = HASB ? bias[ocg * 16 + 2 * q] : 0.f;
        float b1 = HASB ? bias[ocg * 16 + 2 * q + 1] : 0.f;
        out[(size_t)(n * COUT + ocg * 16 + 2 * q) * HW + tid]     = a + b0;
        out[(size_t)(n * COUT + ocg * 16 + 2 * q + 1) * HW + tid] = b + b1;
    }
}

// ---------------- VQ --------------------------------------------------------
// cc[k] = ||codebook_k||^2, correctly rounded (fp64 accumulate -> fp32)
__global__ void cc_kernel(const float* __restrict__ cb) {
    int k = threadIdx.x;  // 256 threads, 1 block
    double s = 0.0;
    for (int d = 0; d < 256; d++) { double v = (double)cb[k * 256 + d]; s = fma(v, v, s); }
    g_cc[k] = (float)s;
}

__device__ __forceinline__ unsigned fenc(float f) {
    unsigned u = __float_as_uint(f);
    return (u & 0x80000000u) ? ~u : (u | 0x80000000u);
}

// One warp per pixel. Emulates the reference fp32 arithmetic:
//   d2_k = fl32( fl32(zz + cc_k) - 2*dot_k )
// with zz correctly rounded (fp64->fp32). First-index tie-break.
__global__ void vq_argmin(const float* __restrict__ dot, const float* __restrict__ z,
                          const float* __restrict__ cb) {
    const int warp = threadIdx.x >> 5, lane = threadIdx.x & 31;
    const int pix = blockIdx.x * 8 + warp;
    const int n = pix >> 8, p = pix & 255;
    const float* dp = dot + (size_t)n * 65536 + p;

    double zzd = 0.0;
    for (int d = lane; d < 256; d += 32) {
        double v = (double)z[(size_t)(n * 256 + d) * 256 + p];
        zzd = fma(v, v, zzd);
    }
#pragma unroll
    for (int o = 16; o; o >>= 1) zzd += __shfl_xor_sync(FULLMASK, zzd, o);
    const float zz = (float)zzd;

    unsigned long long bestK = ~0ull;
#pragma unroll
    for (int q = 0; q < 8; q++) {
        int k = lane + q * 32;
        float t1 = __fadd_rn(zz, g_cc[k]);
        float d2 = __fsub_rn(t1, 2.0f * dp[(size_t)k * 256]);
        unsigned long long key = ((unsigned long long)fenc(d2) << 32) | (unsigned)k;
        if (key < bestK) bestK = key;
    }
#pragma unroll
    for (int o = 16; o; o >>= 1) {
        unsigned long long v = __shfl_xor_sync(FULLMASK, bestK, o);
        if (v < bestK) bestK = v;
    }
    const int j = (int)(bestK & 0xffffffffu);

    float ls = 0.f;
    for (int d = lane; d < 256; d += 32) {
        float zd = z[(size_t)(n * 256 + d) * 256 + p];
        float df = zd - cb[j * 256 + d];
        ls = fmaf(df, df, ls);
    }
#pragma unroll
    for (int o = 16; o; o >>= 1) ls += __shfl_xor_sync(FULLMASK, ls, o);

    __shared__ float wls[8];
    if (lane == 0) { wls[warp] = ls; g_j[pix] = j; }
    __syncthreads();
    if (threadIdx.x == 0) {
        float t = 0.f;
        for (int i = 0; i < 8; i++) t += wls[i];
        g_lossp[blockIdx.x] = t;
    }
}

__global__ void loss_final(float* __restrict__ out) {
    __shared__ float sm[256];
    int t = threadIdx.x;
    float s = 0.f;
    for (int i = t; i < 4096; i += 256) s += g_lossp[i];
    sm[t] = s; __syncthreads();
    for (int o = 128; o; o >>= 1) { if (t < o) sm[t] += sm[t + o]; __syncthreads(); }
    if (t == 0) {
        float L = sm[0] / 32768.f;
        out[0] = L;  // loss_commit
        out[1] = L;  // loss_code (identical in forward)
    }
}

__global__ void vq_gather(const float* __restrict__ cb, float* __restrict__ hq) {
    int i = blockIdx.x * 256 + threadIdx.x;   // 8388608 total
    int p = i & 255, d = (i >> 8) & 255, n = i >> 16;
    hq[i] = cb[g_j[n * 256 + p] * 256 + d];
}

// ---------------- final 3x3 conv (64 -> 3) ----------------------------------
__global__ void conv3x3_out(const float* __restrict__ in, const float* __restrict__ w,
                            const float* __restrict__ bias, float* __restrict__ out) {
    const int n = blockIdx.x, tile = blockIdx.y, tid = threadIdx.x;
    __shared__ float wsm[64][9][4];   // [ic][tap][oc], slot 3 unused (pair align)
    for (int i = tid; i < 3 * 64 * 9; i += 256) {
        int oc = i / 576, r = i % 576;
        wsm[r / 9][r % 9][oc] = w[i];
    }
    __syncthreads();
    u64 acc01[4] = {};
    float acc2[4] = {};
    int oy[4], ox[4];
#pragma unroll
    for (int p = 0; p < 4; p++) {
        int pos = tile * 1024 + p * 256 + tid;
        oy[p] = pos >> 6; ox[p] = pos & 63;
    }
    for (int ic = 0; ic < 64; ic++) {
        const float* ip = in + (size_t)(n * 64 + ic) * 4096;
#pragma unroll
        for (int tap = 0; tap < 9; tap++) {
            const int ky = tap / 3, kx = tap % 3;
            u64 w01 = *reinterpret_cast<const u64*>(&wsm[ic][tap][0]);
            float w2 = wsm[ic][tap][2];
#pragma unroll
            for (int p = 0; p < 4; p++) {
                int iy = oy[p] + ky - 1, ix = ox[p] + kx - 1;
                float v = (iy >= 0 && iy < 64 && ix >= 0 && ix < 64) ? ip[iy * 64 + ix] : 0.f;
                ffma2(acc01[p], pack2(v, v), w01);
                acc2[p] = fmaf(v, w2, acc2[p]);
            }
        }
    }
#pragma unroll
    for (int p = 0; p < 4; p++) {
        float a, b; unpack2(acc01[p], a, b);
        out[(size_t)(n * 3 + 0) * 4096 + oy[p] * 64 + ox[p]] = a + bias[0];
        out[(size_t)(n * 3 + 1) * 4096 + oy[p] * 64 + ox[p]] = b + bias[1];
        out[(size_t)(n * 3 + 2) * 4096 + oy[p] * 64 + ox[p]] = acc2[p] + bias[2];
    }
}

// ---------------------------------------------------------------------------
template<int C, int HW>
static void run_bn(float* buf, const float* g, const float* b) {
    bn_stats<<<dim3(C, NB), 256>>>((const float4*)buf, C, HW / 4);
    bn_final<<<1, 256>>>(C, 1.0f / (128.0f * (float)HW));
    int total4 = 128 * C * HW / 4;
    bn_apply_relu4<C, HW><<<total4 / 256, 256>>>((float4*)buf, g, b);
}

extern "C" void kernel_launch(void* const* d_in, const int* in_sizes, int n_in,
                              void* d_out, int out_size) {
    const float* x    = (const float*)d_in[0];
    const float* cb   = (const float*)d_in[1];
    const float* e_w1 = (const float*)d_in[2];
    const float* e_b1 = (const float*)d_in[3];
    const float* e_g1 = (const float*)d_in[4];
    const float* e_be1= (const float*)d_in[5];
    const float* e_w2 = (const float*)d_in[6];
    const float* e_b2 = (const float*)d_in[7];
    const float* e_g2 = (const float*)d_in[8];
    const float* e_be2= (const float*)d_in[9];
    const float* e_w3 = (const float*)d_in[10];
    const float* e_b3 = (const float*)d_in[11];
    const float* e_g3 = (const float*)d_in[12];
    const float* e_be3= (const float*)d_in[13];
    const float* e_w4 = (const float*)d_in[14];
    const float* e_b4 = (const float*)d_in[15];
    const float* d_w1 = (const float*)d_in[16];
    const float* d_b1 = (const float*)d_in[17];
    const float* d_g1 = (const float*)d_in[18];
    const float* d_be1= (const float*)d_in[19];
    const float* d_w2 = (const float*)d_in[20];
    const float* d_b2 = (const float*)d_in[21];
    const float* d_g2 = (const float*)d_in[22];
    const float* d_be2= (const float*)d_in[23];
    const float* d_w3 = (const float*)d_in[24];
    const float* d_b3 = (const float*)d_in[25];
    const float* d_g3 = (const float*)d_in[26];
    const float* d_be3= (const float*)d_in[27];
    const float* d_w4 = (const float*)d_in[28];
    const float* d_b4 = (const float*)d_in[29];
    float* out = (float*)d_out;

    float *b1, *b2, *b3, *h4, *hq, *dotb;
    cudaGetSymbolAddress((void**)&b1,   g_b1);
    cudaGetSymbolAddress((void**)&b2,   g_b2);
    cudaGetSymbolAddress((void**)&b3,   g_b3);
    cudaGetSymbolAddress((void**)&h4,   g_h4);
    cudaGetSymbolAddress((void**)&hq,   g_hq);
    cudaGetSymbolAddress((void**)&dotb, g_dot);

    // ---------------- encoder ----------------
    conv3x3s1<3, 64, 64, 4><<<dim3(128, 4, 4), 256>>>(x, e_w1, e_b1, b1, 64);
    run_bn<64, 4096>(b1, e_g1, e_be1);

    conv4x4s2<64, 64, 64, 128, 32, 32, 2><<<dim3(128, 8, 2), 256>>>(b1, e_w2, e_b2, b2);
    run_bn<128, 1024>(b2, e_g2, e_be2);

    conv4x4s2<128, 32, 32, 192, 16, 16, 1><<<dim3(128, 12, 1), 256>>>(b2, e_w3, e_b3, b3);
    run_bn<192, 256>(b3, e_g3, e_be3);

    conv1x1<192, 256, 256, false, true><<<dim3(128, 16), 256>>>(b3, e_w4, e_b4, h4);

    // ---------------- vector quantization ----------------
    cc_kernel<<<1, 256>>>(cb);
    conv1x1<256, 256, 256, false, false><<<dim3(128, 16), 256>>>(h4, cb, nullptr, dotb);
    vq_argmin<<<4096, 256>>>(dotb, h4, cb);
    loss_final<<<1, 256>>>(out + (out_size - 2));
    vq_gather<<<32768, 256>>>(cb, hq);

    // ---------------- decoder ----------------
    conv1x1<256, 192, 256, true, true><<<dim3(128, 12), 256>>>(hq, d_w1, d_b1, b3);
    run_bn<192, 256>(b3, d_g1, d_be1);

    convT4x4s2<192, 16, 16, 128, 32, 32, 2><<<dim3(128, 8, 2), 256>>>(b3, d_w2, d_b2, b2);
    run_bn<128, 1024>(b2, d_g2, d_be2);

    convT4x4s2<128, 32, 32, 64, 64, 64, 2><<<dim3(128, 4, 8), 256>>>(b2, d_w3, d_b3, b1);
    run_bn<64, 4096>(b1, d_g3, d_be3);

    conv3x3_out<<<dim3(128, 4), 256>>>(b1, d_w4, d_b4, out);
}